// round 5
// baseline (speedup 1.0000x reference)
#include <cuda_runtime.h>
#include <cuda_fp16.h>
#include <cstdint>

#define EDIM    512
#define FDIM    2048
#define QDIM    8
#define NCHUNK  32          // K chunks of 64
#define NTOKB   256         // 32768 / 128

// ---- device scratch ----
__device__ __align__(128) unsigned char g_w2s[4 * NCHUNK * 16384];   // 2 MB: [nb][c][128n x 64k fp16, SW128]
__device__ __align__(128) unsigned char g_w1b1[73728];               // W1 pairs 64KB + b1 pairs 8KB

#define SWZ(o) ((o) ^ (((o) >> 3) & 0x70))

__device__ __forceinline__ uint32_t smem_u32(const void* p) {
    uint32_t a;
    asm("{ .reg .u64 t; cvta.to.shared.u64 t, %1; cvt.u32.u64 %0, t; }" : "=r"(a) : "l"(p));
    return a;
}
#define MBAR_INIT(a, c) asm volatile("mbarrier.init.shared.b64 [%0], %1;" :: "r"(a), "r"((uint32_t)(c)) : "memory")
#define MBAR_EXPECT(a, n) asm volatile("mbarrier.arrive.expect_tx.shared.b64 _, [%0], %1;" :: "r"(a), "r"((uint32_t)(n)) : "memory")
#define MBAR_ARRIVE(a) asm volatile("mbarrier.arrive.shared.b64 _, [%0];" :: "r"(a) : "memory")
#define MBAR_WAIT(a, ph) do { \
    uint32_t _m = (a), _p = (ph), _d; \
    asm volatile("{ .reg .pred p; mbarrier.try_wait.parity.acquire.cta.shared::cta.b64 p, [%1], %2; selp.b32 %0,1,0,p; }" \
        : "=r"(_d) : "r"(_m), "r"(_p) : "memory"); \
    if (!_d) { \
        asm volatile("{ .reg .pred P1;\nWL_%=:\n mbarrier.try_wait.parity.acquire.cta.shared::cta.b64 P1, [%0], %1, 0x989680;\n @P1 bra.uni WD_%=;\n bra.uni WL_%=;\nWD_%=:\n }" \
            :: "r"(_m), "r"(_p) : "memory"); \
    } } while (0)

__device__ __forceinline__ void bulk_g2s(uint32_t dst, const void* src, uint32_t bytes, uint32_t mbar) {
    asm volatile("cp.async.bulk.shared::cluster.global.mbarrier::complete_tx::bytes [%0], [%1], %2, [%3];"
        :: "r"(dst), "l"(src), "r"(bytes), "r"(mbar) : "memory");
}

#define LDS64(v, a)  asm("ld.shared.b64 %0, [%1];" : "=l"(v) : "r"(a))
#define STS128(a, r0, r1, r2, r3) asm volatile("st.shared.v4.b32 [%0], {%1,%2,%3,%4};" :: "r"(a), "r"(r0), "r"(r1), "r"(r2), "r"(r3) : "memory")
#define FMA2(d, a, b, c) asm("fma.rn.f32x2 %0, %1, %2, %3;" : "=l"(d) : "l"(a), "l"(b), "l"(c))
#define PACK2(d, x)      asm("mov.b64 %0, {%1, %1};" : "=l"(d) : "r"(x))
#define UNPK2(lo, hi, v) asm("mov.b64 {%0, %1}, %2;" : "=r"(lo), "=r"(hi) : "l"(v))

#define LDMX4(r, a) asm volatile( \
    "ldmatrix.sync.aligned.m8n8.x4.shared.b16 {%0,%1,%2,%3}, [%4];" \
    : "=r"((r)[0]), "=r"((r)[1]), "=r"((r)[2]), "=r"((r)[3]) : "r"(a))
#define MMA16816(cf, a, b0, b1) asm volatile( \
    "mma.sync.aligned.m16n8k16.row.col.f32.f16.f16.f32 " \
    "{%0,%1,%2,%3}, {%4,%5,%6,%7}, {%8,%9}, {%0,%1,%2,%3};" \
    : "+f"((cf)[0]), "+f"((cf)[1]), "+f"((cf)[2]), "+f"((cf)[3]) \
    : "r"((a)[0]), "r"((a)[1]), "r"((a)[2]), "r"((a)[3]), "r"(b0), "r"(b1))

// ---------------- prep: W2 -> fp16 swizzled blocks ----------------
__global__ void prep_w2(const float* __restrict__ W2) {
    int idx = blockIdx.x * 256 + threadIdx.x;
    if (idx >= 512 * 256) return;
    int n = idx >> 8, g = idx & 255;
    int k0 = g * 8;
    int nb = n >> 7, nl = n & 127;
    int c = k0 >> 6, kl = k0 & 63;
    const float* s = W2 + (size_t)n * FDIM + k0;
    float4 a = *(const float4*)s;
    float4 b = *(const float4*)(s + 4);
    __half2 p0 = __floats2half2_rn(a.x, a.y);
    __half2 p1 = __floats2half2_rn(a.z, a.w);
    __half2 p2 = __floats2half2_rn(b.x, b.y);
    __half2 p3 = __floats2half2_rn(b.z, b.w);
    uint4 v;
    v.x = *reinterpret_cast<uint32_t*>(&p0);
    v.y = *reinterpret_cast<uint32_t*>(&p1);
    v.z = *reinterpret_cast<uint32_t*>(&p2);
    v.w = *reinterpret_cast<uint32_t*>(&p3);
    uint32_t rel = (uint32_t)(nl * 128 + kl * 2);
    *(uint4*)(g_w2s + ((size_t)(nb * NCHUNK + c) << 14) + SWZ(rel)) = v;
}

// ---------------- prep: W1/b1 paired layout ----------------
__global__ void prep_w1b1(const float* __restrict__ W1, const float* __restrict__ b1) {
    int idx = blockIdx.x * 256 + threadIdx.x;
    if (idx < 8192) {
        int p = idx >> 3, j = idx & 7;
        float2 v;
        v.x = W1[16 * p + j];
        v.y = W1[16 * p + 8 + j];
        *(float2*)(g_w1b1 + p * 64 + j * 8) = v;
    } else if (idx < 9216) {
        int i = idx - 8192;
        float2 v;
        v.x = b1[2 * i];
        v.y = b1[2 * i + 1];
        *(float2*)(g_w1b1 + 65536 + i * 8) = v;
    }
}

// ---------------- fused kernel: quantum + GEMM1 (producers) + GEMM2 (HMMA) ----------------
// SMEM: 3 stage bufs (W2 16K + W1 2K + b1 256B, stride 19456), 2 h bufs (16K), mbars
#define STG_STRIDE 19456
#define STG_BYTES  18688
#define SM_STG 0
#define SM_H   58368
#define SM_MB  91136
#define SMEM_F 91264

__global__ void __launch_bounds__(384)
ffq_fused(const float* __restrict__ x, const float* __restrict__ theta,
          const float* __restrict__ b2, float* __restrict__ out) {
    extern __shared__ char smem[];
    const uint32_t sb = smem_u32(smem);
    const int tid = threadIdx.x, wid = tid >> 5, lane = tid & 31;
    const int nb = blockIdx.x, tb = blockIdx.y;

    const uint32_t mb_sf = sb + SM_MB;        // stage_full[3]
    const uint32_t mb_se = sb + SM_MB + 24;   // stage_empty[3]
    const uint32_t mb_hf = sb + SM_MB + 48;   // h_full[2]
    const uint32_t mb_he = sb + SM_MB + 64;   // h_empty[2]

    if (tid == 0) {
#pragma unroll
        for (int s = 0; s < 3; ++s) { MBAR_INIT(mb_sf + s * 8, 1); MBAR_INIT(mb_se + s * 8, 12); }
#pragma unroll
        for (int b = 0; b < 2; ++b) { MBAR_INIT(mb_hf + b * 8, 4); MBAR_INIT(mb_he + b * 8, 8); }
    }
    __syncthreads();
    if (tid == 0) {
#pragma unroll
        for (int s = 0; s < 3; ++s) {
            MBAR_EXPECT(mb_sf + s * 8, STG_BYTES);
            bulk_g2s(sb + SM_STG + s * STG_STRIDE, g_w2s + ((size_t)(nb * NCHUNK + s) << 14), 16384, mb_sf + s * 8);
            bulk_g2s(sb + SM_STG + s * STG_STRIDE + 16384, g_w1b1 + s * 2048, 2048, mb_sf + s * 8);
            bulk_g2s(sb + SM_STG + s * STG_STRIDE + 18432, g_w1b1 + 65536 + s * 256, 256, mb_sf + s * 8);
        }
    }

    if (wid >= 8) {
        // ---------------- producer warps (8..11): h chunks ----------------
        const int e0 = (wid - 8) * 8;      // 8 f-pairs per warp per chunk
        unsigned long long q2[4][8];
        {
            float cth[8];
#pragma unroll
            for (int j = 0; j < 8; ++j) cth[j] = __cosf(__ldg(theta + j));
#pragma unroll
            for (int r = 0; r < 4; ++r) {
                const int tok = tb * 128 + r * 32 + lane;
                float4 xa = *(const float4*)(x + (size_t)tok * EDIM);
                float4 xb = *(const float4*)(x + (size_t)tok * EDIM + 4);
                float xv[8] = {xa.x, xa.y, xa.z, xa.w, xb.x, xb.y, xb.z, xb.w};
#pragma unroll
                for (int j = 0; j < 8; ++j)
                    PACK2(q2[r][j], __float_as_uint(__cosf(xv[j]) * cth[j]));
            }
        }
        const __half2 hzero = __float2half2_rn(0.0f);
        for (int c = 0; c < NCHUNK; ++c) {
            const int sbuf = c % 3, hb = c & 1;
            MBAR_WAIT(mb_sf + sbuf * 8, (c / 3) & 1);
            if (c >= 2) MBAR_WAIT(mb_he + hb * 8, ((c - 2) >> 1) & 1);
            const uint32_t w1a = sb + SM_STG + sbuf * STG_STRIDE + 16384;
            const uint32_t b1a = w1a + 2048;
            const uint32_t hbase = sb + SM_H + hb * 16384;
            uint32_t outv[4][8];
#pragma unroll
            for (int e = 0; e < 8; ++e) {
                const int pe = e0 + e;
                unsigned long long bp, wp[8];
                LDS64(bp, b1a + pe * 8);
                const uint32_t wb = w1a + pe * 64;
#pragma unroll
                for (int j = 0; j < 8; ++j) LDS64(wp[j], wb + j * 8);
#pragma unroll
                for (int r = 0; r < 4; ++r) {
                    unsigned long long acc = bp;
#pragma unroll
                    for (int j = 0; j < 8; ++j) FMA2(acc, q2[r][j], wp[j], acc);
                    uint32_t lo, hi;
                    UNPK2(lo, hi, acc);
                    __half2 hh = __hmax2(__floats2half2_rn(__uint_as_float(lo), __uint_as_float(hi)), hzero);
                    outv[r][e] = *reinterpret_cast<uint32_t*>(&hh);
                }
            }
#pragma unroll
            for (int r = 0; r < 4; ++r) {
                const uint32_t rel = (uint32_t)((r * 32 + lane) * 128 + e0 * 4);
                STS128(hbase + SWZ(rel), outv[r][0], outv[r][1], outv[r][2], outv[r][3]);
                STS128(hbase + SWZ(rel + 16), outv[r][4], outv[r][5], outv[r][6], outv[r][7]);
            }
            __syncwarp();
            if (lane == 0) { MBAR_ARRIVE(mb_hf + hb * 8); MBAR_ARRIVE(mb_se + sbuf * 8); }
        }
    } else {
        // ---------------- MMA warps (0..7): GEMM2 ----------------
        const int wm = wid & 1, wn = wid >> 1;
        float cf[16][4];
#pragma unroll
        for (int f = 0; f < 16; ++f)
#pragma unroll
            for (int i = 0; i < 4; ++i) cf[f][i] = 0.0f;

        const uint32_t arow = (uint32_t)(wm * 64 + (lane & 15));
        const uint32_t abyte = (uint32_t)((lane >> 4) * 16);
        const uint32_t brow = (uint32_t)(wn * 32 + (lane & 7) + ((lane >> 4) & 1) * 8);
        const uint32_t bbyte = (uint32_t)(((lane >> 3) & 1) * 16);

        for (int c = 0; c < NCHUNK; ++c) {
            const int sbuf = c % 3, hb = c & 1;
            MBAR_WAIT(mb_sf + sbuf * 8, (c / 3) & 1);
            MBAR_WAIT(mb_hf + hb * 8, (c >> 1) & 1);
            const uint32_t abase = sb + SM_H + hb * 16384;
            const uint32_t bbase = sb + SM_STG + sbuf * STG_STRIDE;
#pragma unroll
            for (int k = 0; k < 4; ++k) {
                uint32_t af[4][4], bf[2][4];
#pragma unroll
                for (int mi = 0; mi < 4; ++mi)
                    LDMX4(af[mi], abase + SWZ((arow + mi * 16) * 128 + k * 32 + abyte));
#pragma unroll
                for (int bi = 0; bi < 2; ++bi)
                    LDMX4(bf[bi], bbase + SWZ((brow + bi * 16) * 128 + k * 32 + bbyte));
#pragma unroll
                for (int mi = 0; mi < 4; ++mi)
#pragma unroll
                    for (int ni = 0; ni < 4; ++ni)
                        MMA16816(cf[mi * 4 + ni], af[mi], bf[ni >> 1][(ni & 1) * 2], bf[ni >> 1][(ni & 1) * 2 + 1]);
            }
            __syncwarp();
            if (lane == 0) { MBAR_ARRIVE(mb_he + hb * 8); MBAR_ARRIVE(mb_se + sbuf * 8); }

            if (tid == 0 && c + 3 < NCHUNK) {
                MBAR_WAIT(mb_se + sbuf * 8, (c / 3) & 1);   // all 12 warps released buffer
                MBAR_EXPECT(mb_sf + sbuf * 8, STG_BYTES);
                const int s = c + 3;
                bulk_g2s(sb + SM_STG + sbuf * STG_STRIDE, g_w2s + ((size_t)(nb * NCHUNK + s) << 14), 16384, mb_sf + sbuf * 8);
                bulk_g2s(sb + SM_STG + sbuf * STG_STRIDE + 16384, g_w1b1 + s * 2048, 2048, mb_sf + sbuf * 8);
                bulk_g2s(sb + SM_STG + sbuf * STG_STRIDE + 18432, g_w1b1 + 65536 + s * 256, 256, mb_sf + sbuf * 8);
            }
        }

        // epilogue
        const int rowbase = tb * 128 + wm * 64 + (lane >> 2);
        const int colbase = nb * 128 + wn * 32 + (lane & 3) * 2;
#pragma unroll
        for (int mi = 0; mi < 4; ++mi) {
#pragma unroll
            for (int ni = 0; ni < 4; ++ni) {
                const int f = mi * 4 + ni;
                const int col = colbase + ni * 8;
                const float2 bv = *(const float2*)(b2 + col);
                const int r0 = rowbase + mi * 16;
                float2 o0, o1;
                o0.x = cf[f][0] + bv.x; o0.y = cf[f][1] + bv.y;
                o1.x = cf[f][2] + bv.x; o1.y = cf[f][3] + bv.y;
                *(float2*)(out + (size_t)r0 * EDIM + col) = o0;
                *(float2*)(out + (size_t)(r0 + 8) * EDIM + col) = o1;
            }
        }
    }
}

extern "C" void kernel_launch(void* const* d_in, const int* in_sizes, int n_in,
                              void* d_out, int out_size) {
    const float* x     = (const float*)d_in[0];
    const float* theta = (const float*)d_in[1];
    const float* W1    = (const float*)d_in[2];
    const float* b1    = (const float*)d_in[3];
    const float* W2    = (const float*)d_in[4];
    const float* b2    = (const float*)d_in[5];
    float* out = (float*)d_out;

    cudaFuncSetAttribute(ffq_fused, cudaFuncAttributeMaxDynamicSharedMemorySize, SMEM_F);

    prep_w2<<<512, 256>>>(W2);
    prep_w1b1<<<36, 256>>>(W1, b1);
    ffq_fused<<<dim3(4, NTOKB), 384, SMEM_F>>>(x, theta, b2, out);
}

// round 6
// speedup vs baseline: 1.4457x; 1.4457x over previous
#include <cuda_runtime.h>
#include <cuda_fp16.h>
#include <cstdint>

#define EDIM    512
#define FDIM    2048
#define QDIM    8
#define NCHUNK  32          // K chunks of 64
#define NTOKB   256         // 32768 / 128

// ---- device scratch ----
__device__ __align__(128) unsigned char g_w2s[4 * NCHUNK * 16384];   // 2 MB: [nb][c][128n x 64k fp16, SW128]
__device__ __align__(128) unsigned char g_h[NTOKB * NCHUNK * 16384]; // 128 MB: [tb][c][128m x 64k fp16, SW128]

#define SWZ(o) ((o) ^ (((o) >> 3) & 0x70))

__device__ __forceinline__ uint32_t smem_u32(const void* p) {
    uint32_t a;
    asm("{ .reg .u64 t; cvta.to.shared.u64 t, %1; cvt.u32.u64 %0, t; }" : "=r"(a) : "l"(p));
    return a;
}
#define MBAR_INIT(a, c) asm volatile("mbarrier.init.shared.b64 [%0], %1;" :: "r"(a), "r"((uint32_t)(c)) : "memory")
#define MBAR_EXPECT(a, n) asm volatile("mbarrier.arrive.expect_tx.shared.b64 _, [%0], %1;" :: "r"(a), "r"((uint32_t)(n)) : "memory")
#define MBAR_ARRIVE(a) asm volatile("mbarrier.arrive.shared.b64 _, [%0];" :: "r"(a) : "memory")
#define MBAR_WAIT(a, ph) do { \
    uint32_t _m = (a), _p = (ph), _d; \
    asm volatile("{ .reg .pred p; mbarrier.try_wait.parity.acquire.cta.shared::cta.b64 p, [%1], %2; selp.b32 %0,1,0,p; }" \
        : "=r"(_d) : "r"(_m), "r"(_p) : "memory"); \
    if (!_d) { \
        asm volatile("{ .reg .pred P1;\nWL_%=:\n mbarrier.try_wait.parity.acquire.cta.shared::cta.b64 P1, [%0], %1, 0x989680;\n @P1 bra.uni WD_%=;\n bra.uni WL_%=;\nWD_%=:\n }" \
            :: "r"(_m), "r"(_p) : "memory"); \
    } } while (0)

__device__ __forceinline__ void bulk_g2s(uint32_t dst, const void* src, uint32_t bytes, uint32_t mbar) {
    asm volatile("cp.async.bulk.shared::cluster.global.mbarrier::complete_tx::bytes [%0], [%1], %2, [%3];"
        :: "r"(dst), "l"(src), "r"(bytes), "r"(mbar) : "memory");
}
__device__ __forceinline__ void bulk_s2g(void* dst, uint32_t src, uint32_t bytes) {
    asm volatile("cp.async.bulk.global.shared::cta.bulk_group [%0], [%1], %2;"
        :: "l"(dst), "r"(src), "r"(bytes) : "memory");
}
#define BULK_COMMIT() asm volatile("cp.async.bulk.commit_group;" ::: "memory")
#define BULK_WAIT(n)  asm volatile("cp.async.bulk.wait_group %0;" :: "n"(n) : "memory")
#define FENCE_ASYNC() asm volatile("fence.proxy.async.shared::cta;" ::: "memory")

#define LDS64(v, a)  asm("ld.shared.b64 %0, [%1];" : "=l"(v) : "r"(a))
#define STS128(a, r0, r1, r2, r3) asm volatile("st.shared.v4.b32 [%0], {%1,%2,%3,%4};" :: "r"(a), "r"(r0), "r"(r1), "r"(r2), "r"(r3) : "memory")
#define FMA2(d, a, b, c) asm("fma.rn.f32x2 %0, %1, %2, %3;" : "=l"(d) : "l"(a), "l"(b), "l"(c))
#define PACK2(d, x)      asm("mov.b64 %0, {%1, %1};" : "=l"(d) : "r"(x))
#define UNPK2(lo, hi, v) asm("mov.b64 {%0, %1}, %2;" : "=r"(lo), "=r"(hi) : "l"(v))

#define LDMX4(r, a) asm volatile( \
    "ldmatrix.sync.aligned.m8n8.x4.shared.b16 {%0,%1,%2,%3}, [%4];" \
    : "=r"((r)[0]), "=r"((r)[1]), "=r"((r)[2]), "=r"((r)[3]) : "r"(a))
#define MMA16816(cf, a, b0, b1) asm volatile( \
    "mma.sync.aligned.m16n8k16.row.col.f32.f16.f16.f32 " \
    "{%0,%1,%2,%3}, {%4,%5,%6,%7}, {%8,%9}, {%0,%1,%2,%3};" \
    : "+f"((cf)[0]), "+f"((cf)[1]), "+f"((cf)[2]), "+f"((cf)[3]) \
    : "r"((a)[0]), "r"((a)[1]), "r"((a)[2]), "r"((a)[3]), "r"(b0), "r"(b1))

// ---------------- kernel A: W2 prep + W1/b1 build + h = relu(q.W1^T + b1) ----------------
// smem: [0,65536) W1 pairs; [65536,73728) b1 pairs; h tiles at 73792
#define SA_HT   73792
#define SMEM_A  (SA_HT + 2 * 16384)

__global__ void __launch_bounds__(256)
ffq_h(const float* __restrict__ x, const float* __restrict__ theta,
      const float* __restrict__ W1, const float* __restrict__ b1,
      const float* __restrict__ W2) {
    extern __shared__ char smem[];
    const uint32_t sb = smem_u32(smem);
    const int tid = threadIdx.x, wid = tid >> 5, lane = tid & 31;
    const int tb = blockIdx.x;

    // ---- embedded W2 prep: this CTA swizzles 512 of 131072 groups ----
    {
        const int base = tb * 512;
        for (int t = tid; t < 512; t += 256) {
            const int idx = base + t;
            const int n = idx >> 8, g = idx & 255;
            const int k0 = g * 8;
            const int nb = n >> 7, nl = n & 127;
            const int c = k0 >> 6, kl = k0 & 63;
            const float* s = W2 + (size_t)n * FDIM + k0;
            float4 a = *(const float4*)s;
            float4 b = *(const float4*)(s + 4);
            __half2 p0 = __floats2half2_rn(a.x, a.y);
            __half2 p1 = __floats2half2_rn(a.z, a.w);
            __half2 p2 = __floats2half2_rn(b.x, b.y);
            __half2 p3 = __floats2half2_rn(b.z, b.w);
            uint4 v;
            v.x = *reinterpret_cast<uint32_t*>(&p0);
            v.y = *reinterpret_cast<uint32_t*>(&p1);
            v.z = *reinterpret_cast<uint32_t*>(&p2);
            v.w = *reinterpret_cast<uint32_t*>(&p3);
            uint32_t rel = (uint32_t)(nl * 128 + kl * 2);
            *(uint4*)(g_w2s + ((size_t)(nb * NCHUNK + c) << 14) + SWZ(rel)) = v;
        }
    }

    // ---- build W1 pair + b1 pair layout in smem ----
    for (int p = tid; p < 1024; p += 256) {
        float4 r0a = *(const float4*)(W1 + 16 * p);
        float4 r0b = *(const float4*)(W1 + 16 * p + 4);
        float4 r1a = *(const float4*)(W1 + 16 * p + 8);
        float4 r1b = *(const float4*)(W1 + 16 * p + 12);
        float2* dst = (float2*)(smem + p * 64);
        dst[0] = make_float2(r0a.x, r1a.x);
        dst[1] = make_float2(r0a.y, r1a.y);
        dst[2] = make_float2(r0a.z, r1a.z);
        dst[3] = make_float2(r0a.w, r1a.w);
        dst[4] = make_float2(r0b.x, r1b.x);
        dst[5] = make_float2(r0b.y, r1b.y);
        dst[6] = make_float2(r0b.z, r1b.z);
        dst[7] = make_float2(r0b.w, r1b.w);
        ((float2*)(smem + 65536))[p] = ((const float2*)b1)[p];
    }

    // q[r][j] = cos(x)*cos(theta), packed {q,q}; tokens: tb*128 + r*32 + lane
    unsigned long long q2[4][8];
    {
        float cth[8];
#pragma unroll
        for (int j = 0; j < 8; ++j) cth[j] = __cosf(__ldg(theta + j));
#pragma unroll
        for (int r = 0; r < 4; ++r) {
            const int tok = tb * 128 + r * 32 + lane;
            float4 xa = *(const float4*)(x + (size_t)tok * EDIM);
            float4 xb = *(const float4*)(x + (size_t)tok * EDIM + 4);
            float xv[8] = {xa.x, xa.y, xa.z, xa.w, xb.x, xb.y, xb.z, xb.w};
#pragma unroll
            for (int j = 0; j < 8; ++j)
                PACK2(q2[r][j], __float_as_uint(__cosf(xv[j]) * cth[j]));
        }
    }
    __syncthreads();

    const __half2 hzero = __float2half2_rn(0.0f);
    for (int c = 0; c < NCHUNK; ++c) {
        const uint32_t hbase = sb + SA_HT + (c & 1) * 16384;
        if (c >= 2) {
            if (tid == 0) BULK_WAIT(1);
            __syncthreads();
        }
        const uint32_t prb = (uint32_t)(c * 32 + wid * 4);
        uint32_t hv[4][4];
#pragma unroll
        for (int e = 0; e < 4; ++e) {
            unsigned long long bp, wp[8];
            LDS64(bp, sb + 65536 + (prb + e) * 8);
            const uint32_t wb = sb + (prb + e) * 64;
#pragma unroll
            for (int j = 0; j < 8; ++j) LDS64(wp[j], wb + j * 8);
#pragma unroll
            for (int r = 0; r < 4; ++r) {
                unsigned long long acc = bp;
#pragma unroll
                for (int j = 0; j < 8; ++j) FMA2(acc, q2[r][j], wp[j], acc);
                uint32_t lo, hi;
                UNPK2(lo, hi, acc);
                __half2 hh = __hmax2(__floats2half2_rn(__uint_as_float(lo), __uint_as_float(hi)), hzero);
                hv[r][e] = *reinterpret_cast<uint32_t*>(&hh);
            }
        }
#pragma unroll
        for (int r = 0; r < 4; ++r) {
            const uint32_t rel = (uint32_t)((r * 32 + lane) * 128 + wid * 16);
            STS128(hbase + SWZ(rel), hv[r][0], hv[r][1], hv[r][2], hv[r][3]);
        }
        __syncthreads();
        if (tid == 0) {
            FENCE_ASYNC();
            bulk_s2g(g_h + ((size_t)(tb * NCHUNK + c) << 14), hbase, 16384);
            BULK_COMMIT();
        }
    }
    if (tid == 0) BULK_WAIT(0);
}

// ---------------- kernel B: out = h @ W2^T + b2 (HMMA, 3-stage, reg-pipelined) ----------------
#define SB_FULL 98304
#define SB_CONS 98328
#define SMEM_B  98368

#define LOADK(s, k) do { \
    _Pragma("unroll") \
    for (int mi = 0; mi < 4; ++mi) \
        LDMX4(af[s][mi], abase + SWZ((arow + mi * 16) * 128 + (k) * 32 + abyte)); \
    _Pragma("unroll") \
    for (int bi = 0; bi < 2; ++bi) \
        LDMX4(bf[s][bi], bbase + SWZ((brow + bi * 16) * 128 + (k) * 32 + bbyte)); \
} while (0)

__global__ void __launch_bounds__(256, 2)
ffq_gemm(const float* __restrict__ b2, float* __restrict__ out) {
    extern __shared__ char smem[];
    const uint32_t sb = smem_u32(smem);
    const int tid = threadIdx.x, wid = tid >> 5, lane = tid & 31;
    const int nb = blockIdx.x, tb = blockIdx.y;
    const int wm = wid & 1, wn = wid >> 1;

    if (tid == 0) {
#pragma unroll
        for (int s = 0; s < 3; ++s) {
            MBAR_INIT(sb + SB_FULL + s * 8, 1);
            MBAR_INIT(sb + SB_CONS + s * 8, 8);
        }
    }
    __syncthreads();

    if (tid == 0) {
#pragma unroll
        for (int s = 0; s < 3; ++s) {
            MBAR_EXPECT(sb + SB_FULL + s * 8, 32768);
            bulk_g2s(sb + s * 32768, g_h + ((size_t)(tb * NCHUNK + s) << 14), 16384, sb + SB_FULL + s * 8);
            bulk_g2s(sb + s * 32768 + 16384, g_w2s + ((size_t)(nb * NCHUNK + s) << 14), 16384, sb + SB_FULL + s * 8);
        }
    }

    float cf[16][4];
#pragma unroll
    for (int f = 0; f < 16; ++f)
#pragma unroll
        for (int i = 0; i < 4; ++i) cf[f][i] = 0.0f;

    const uint32_t arow = (uint32_t)(wm * 64 + (lane & 15));
    const uint32_t abyte = (uint32_t)((lane >> 4) * 16);
    const uint32_t brow = (uint32_t)(wn * 32 + (lane & 7) + ((lane >> 4) & 1) * 8);
    const uint32_t bbyte = (uint32_t)(((lane >> 3) & 1) * 16);

    int buf = 0, ph = 0;
    for (int c = 0; c < NCHUNK; ++c) {
        MBAR_WAIT(sb + SB_FULL + buf * 8, ph);
        const uint32_t abase = sb + buf * 32768;
        const uint32_t bbase = abase + 16384;

        uint32_t af[2][4][4], bf[2][2][4];
        LOADK(0, 0);
#pragma unroll
        for (int k = 0; k < 4; ++k) {
            const int cur = k & 1;
            if (k < 3) {
                const int nxt = cur ^ 1;
                LOADK(nxt, k + 1);
            }
#pragma unroll
            for (int mi = 0; mi < 4; ++mi)
#pragma unroll
                for (int ni = 0; ni < 4; ++ni)
                    MMA16816(cf[mi * 4 + ni], af[cur][mi], bf[cur][ni >> 1][(ni & 1) * 2], bf[cur][ni >> 1][(ni & 1) * 2 + 1]);
        }
        __syncwarp();
        if (lane == 0) MBAR_ARRIVE(sb + SB_CONS + buf * 8);

        if (tid == 0 && c + 3 < NCHUNK) {
            const int s = c + 3;
            MBAR_WAIT(sb + SB_CONS + buf * 8, ph);
            MBAR_EXPECT(sb + SB_FULL + buf * 8, 32768);
            bulk_g2s(sb + buf * 32768, g_h + ((size_t)(tb * NCHUNK + s) << 14), 16384, sb + SB_FULL + buf * 8);
            bulk_g2s(sb + buf * 32768 + 16384, g_w2s + ((size_t)(nb * NCHUNK + s) << 14), 16384, sb + SB_FULL + buf * 8);
        }
        if (++buf == 3) { buf = 0; ph ^= 1; }
    }

    // epilogue
    const int rowbase = tb * 128 + wm * 64 + (lane >> 2);
    const int colbase = nb * 128 + wn * 32 + (lane & 3) * 2;
#pragma unroll
    for (int mi = 0; mi < 4; ++mi) {
#pragma unroll
        for (int ni = 0; ni < 4; ++ni) {
            const int f = mi * 4 + ni;
            const int col = colbase + ni * 8;
            const float2 bv = *(const float2*)(b2 + col);
            const int r0 = rowbase + mi * 16;
            float2 o0, o1;
            o0.x = cf[f][0] + bv.x; o0.y = cf[f][1] + bv.y;
            o1.x = cf[f][2] + bv.x; o1.y = cf[f][3] + bv.y;
            *(float2*)(out + (size_t)r0 * EDIM + col) = o0;
            *(float2*)(out + (size_t)(r0 + 8) * EDIM + col) = o1;
        }
    }
}

extern "C" void kernel_launch(void* const* d_in, const int* in_sizes, int n_in,
                              void* d_out, int out_size) {
    const float* x     = (const float*)d_in[0];
    const float* theta = (const float*)d_in[1];
    const float* W1    = (const float*)d_in[2];
    const float* b1    = (const float*)d_in[3];
    const float* W2    = (const float*)d_in[4];
    const float* b2    = (const float*)d_in[5];
    float* out = (float*)d_out;

    cudaFuncSetAttribute(ffq_h, cudaFuncAttributeMaxDynamicSharedMemorySize, SMEM_A);
    cudaFuncSetAttribute(ffq_gemm, cudaFuncAttributeMaxDynamicSharedMemorySize, SMEM_B);

    ffq_h<<<NTOKB, 256, SMEM_A>>>(x, theta, W1, b1, W2);
    ffq_gemm<<<dim3(4, NTOKB), 256, SMEM_B>>>(b2, out);
}

// round 7
// speedup vs baseline: 1.4666x; 1.0145x over previous
#include <cuda_runtime.h>
#include <cuda_fp16.h>
#include <cstdint>

#define EDIM    512
#define FDIM    2048
#define QDIM    8
#define NCHUNK  32          // K chunks of 64
#define NTOKB   256         // 32768 / 128
#define NTILES  1024        // 4 nb x 256 tb
#define NWORKER 296         // 2 per SM

// ---- device scratch ----
__device__ __align__(128) unsigned char g_w2s[4 * NCHUNK * 16384];   // 2 MB
__device__ __align__(128) unsigned char g_h[NTOKB * NCHUNK * 16384]; // 128 MB
__device__ int g_ctr;

#define SWZ(o) ((o) ^ (((o) >> 3) & 0x70))

__device__ __forceinline__ uint32_t smem_u32(const void* p) {
    uint32_t a;
    asm("{ .reg .u64 t; cvta.to.shared.u64 t, %1; cvt.u32.u64 %0, t; }" : "=r"(a) : "l"(p));
    return a;
}
#define MBAR_INIT(a, c) asm volatile("mbarrier.init.shared.b64 [%0], %1;" :: "r"(a), "r"((uint32_t)(c)) : "memory")
#define MBAR_EXPECT(a, n) asm volatile("mbarrier.arrive.expect_tx.shared.b64 _, [%0], %1;" :: "r"(a), "r"((uint32_t)(n)) : "memory")
#define MBAR_ARRIVE(a) asm volatile("mbarrier.arrive.shared.b64 _, [%0];" :: "r"(a) : "memory")
#define MBAR_WAIT(a, ph) do { \
    uint32_t _m = (a), _p = (ph), _d; \
    asm volatile("{ .reg .pred p; mbarrier.try_wait.parity.acquire.cta.shared::cta.b64 p, [%1], %2; selp.b32 %0,1,0,p; }" \
        : "=r"(_d) : "r"(_m), "r"(_p) : "memory"); \
    if (!_d) { \
        asm volatile("{ .reg .pred P1;\nWL_%=:\n mbarrier.try_wait.parity.acquire.cta.shared::cta.b64 P1, [%0], %1, 0x989680;\n @P1 bra.uni WD_%=;\n bra.uni WL_%=;\nWD_%=:\n }" \
            :: "r"(_m), "r"(_p) : "memory"); \
    } } while (0)

__device__ __forceinline__ void bulk_g2s(uint32_t dst, const void* src, uint32_t bytes, uint32_t mbar) {
    asm volatile("cp.async.bulk.shared::cluster.global.mbarrier::complete_tx::bytes [%0], [%1], %2, [%3];"
        :: "r"(dst), "l"(src), "r"(bytes), "r"(mbar) : "memory");
}
__device__ __forceinline__ void bulk_s2g(void* dst, uint32_t src, uint32_t bytes) {
    asm volatile("cp.async.bulk.global.shared::cta.bulk_group [%0], [%1], %2;"
        :: "l"(dst), "r"(src), "r"(bytes) : "memory");
}
#define BULK_COMMIT() asm volatile("cp.async.bulk.commit_group;" ::: "memory")
#define BULK_WAIT(n)  asm volatile("cp.async.bulk.wait_group %0;" :: "n"(n) : "memory")
#define FENCE_ASYNC() asm volatile("fence.proxy.async.shared::cta;" ::: "memory")

#define LDS64(v, a)  asm("ld.shared.b64 %0, [%1];" : "=l"(v) : "r"(a))
#define STS128(a, r0, r1, r2, r3) asm volatile("st.shared.v4.b32 [%0], {%1,%2,%3,%4};" :: "r"(a), "r"(r0), "r"(r1), "r"(r2), "r"(r3) : "memory")
#define FMA2(d, a, b, c) asm("fma.rn.f32x2 %0, %1, %2, %3;" : "=l"(d) : "l"(a), "l"(b), "l"(c))
#define PACK2(d, x)      asm("mov.b64 %0, {%1, %1};" : "=l"(d) : "r"(x))
#define UNPK2(lo, hi, v) asm("mov.b64 {%0, %1}, %2;" : "=r"(lo), "=r"(hi) : "l"(v))

#define LDMX4(r, a) asm volatile( \
    "ldmatrix.sync.aligned.m8n8.x4.shared.b16 {%0,%1,%2,%3}, [%4];" \
    : "=r"((r)[0]), "=r"((r)[1]), "=r"((r)[2]), "=r"((r)[3]) : "r"(a))
#define MMA16816(cf, a, b0, b1) asm volatile( \
    "mma.sync.aligned.m16n8k16.row.col.f32.f16.f16.f32 " \
    "{%0,%1,%2,%3}, {%4,%5,%6,%7}, {%8,%9}, {%0,%1,%2,%3};" \
    : "+f"((cf)[0]), "+f"((cf)[1]), "+f"((cf)[2]), "+f"((cf)[3]) \
    : "r"((a)[0]), "r"((a)[1]), "r"((a)[2]), "r"((a)[3]), "r"(b0), "r"(b1))

// ---------------- kernel A: W2 prep + W1/b1 build + h = relu(q.W1^T + b1) ----------------
#define SA_HT   73792
#define SMEM_A  (SA_HT + 2 * 16384)

__global__ void __launch_bounds__(256)
ffq_h(const float* __restrict__ x, const float* __restrict__ theta,
      const float* __restrict__ W1, const float* __restrict__ b1,
      const float* __restrict__ W2) {
    extern __shared__ char smem[];
    const uint32_t sb = smem_u32(smem);
    const int tid = threadIdx.x, wid = tid >> 5, lane = tid & 31;
    const int tb = blockIdx.x;

    if (tb == 0 && tid == 0) g_ctr = 0;   // reset persistent-gemm tile counter

    // ---- embedded W2 prep: this CTA swizzles 512 of 131072 groups ----
    {
        const int base = tb * 512;
        for (int t = tid; t < 512; t += 256) {
            const int idx = base + t;
            const int n = idx >> 8, g = idx & 255;
            const int k0 = g * 8;
            const int nb = n >> 7, nl = n & 127;
            const int c = k0 >> 6, kl = k0 & 63;
            const float* s = W2 + (size_t)n * FDIM + k0;
            float4 a = *(const float4*)s;
            float4 b = *(const float4*)(s + 4);
            __half2 p0 = __floats2half2_rn(a.x, a.y);
            __half2 p1 = __floats2half2_rn(a.z, a.w);
            __half2 p2 = __floats2half2_rn(b.x, b.y);
            __half2 p3 = __floats2half2_rn(b.z, b.w);
            uint4 v;
            v.x = *reinterpret_cast<uint32_t*>(&p0);
            v.y = *reinterpret_cast<uint32_t*>(&p1);
            v.z = *reinterpret_cast<uint32_t*>(&p2);
            v.w = *reinterpret_cast<uint32_t*>(&p3);
            uint32_t rel = (uint32_t)(nl * 128 + kl * 2);
            *(uint4*)(g_w2s + ((size_t)(nb * NCHUNK + c) << 14) + SWZ(rel)) = v;
        }
    }

    // ---- build W1 pair + b1 pair layout in smem ----
    for (int p = tid; p < 1024; p += 256) {
        float4 r0a = *(const float4*)(W1 + 16 * p);
        float4 r0b = *(const float4*)(W1 + 16 * p + 4);
        float4 r1a = *(const float4*)(W1 + 16 * p + 8);
        float4 r1b = *(const float4*)(W1 + 16 * p + 12);
        float2* dst = (float2*)(smem + p * 64);
        dst[0] = make_float2(r0a.x, r1a.x);
        dst[1] = make_float2(r0a.y, r1a.y);
        dst[2] = make_float2(r0a.z, r1a.z);
        dst[3] = make_float2(r0a.w, r1a.w);
        dst[4] = make_float2(r0b.x, r1b.x);
        dst[5] = make_float2(r0b.y, r1b.y);
        dst[6] = make_float2(r0b.z, r1b.z);
        dst[7] = make_float2(r0b.w, r1b.w);
        ((float2*)(smem + 65536))[p] = ((const float2*)b1)[p];
    }

    unsigned long long q2[4][8];
    {
        float cth[8];
#pragma unroll
        for (int j = 0; j < 8; ++j) cth[j] = __cosf(__ldg(theta + j));
#pragma unroll
        for (int r = 0; r < 4; ++r) {
            const int tok = tb * 128 + r * 32 + lane;
            float4 xa = *(const float4*)(x + (size_t)tok * EDIM);
            float4 xb = *(const float4*)(x + (size_t)tok * EDIM + 4);
            float xv[8] = {xa.x, xa.y, xa.z, xa.w, xb.x, xb.y, xb.z, xb.w};
#pragma unroll
            for (int j = 0; j < 8; ++j)
                PACK2(q2[r][j], __float_as_uint(__cosf(xv[j]) * cth[j]));
        }
    }
    __syncthreads();

    const __half2 hzero = __float2half2_rn(0.0f);
    for (int c = 0; c < NCHUNK; ++c) {
        const uint32_t hbase = sb + SA_HT + (c & 1) * 16384;
        if (c >= 2) {
            if (tid == 0) BULK_WAIT(1);
            __syncthreads();
        }
        const uint32_t prb = (uint32_t)(c * 32 + wid * 4);
        uint32_t hv[4][4];
#pragma unroll
        for (int e = 0; e < 4; ++e) {
            unsigned long long bp, wp[8];
            LDS64(bp, sb + 65536 + (prb + e) * 8);
            const uint32_t wb = sb + (prb + e) * 64;
#pragma unroll
            for (int j = 0; j < 8; ++j) LDS64(wp[j], wb + j * 8);
#pragma unroll
            for (int r = 0; r < 4; ++r) {
                unsigned long long acc = bp;
#pragma unroll
                for (int j = 0; j < 8; ++j) FMA2(acc, q2[r][j], wp[j], acc);
                uint32_t lo, hi;
                UNPK2(lo, hi, acc);
                __half2 hh = __hmax2(__floats2half2_rn(__uint_as_float(lo), __uint_as_float(hi)), hzero);
                hv[r][e] = *reinterpret_cast<uint32_t*>(&hh);
            }
        }
#pragma unroll
        for (int r = 0; r < 4; ++r) {
            const uint32_t rel = (uint32_t)((r * 32 + lane) * 128 + wid * 16);
            STS128(hbase + SWZ(rel), hv[r][0], hv[r][1], hv[r][2], hv[r][3]);
        }
        __syncthreads();
        if (tid == 0) {
            FENCE_ASYNC();
            bulk_s2g(g_h + ((size_t)(tb * NCHUNK + c) << 14), hbase, 16384);
            BULK_COMMIT();
        }
    }
    if (tid == 0) BULK_WAIT(0);
}

// ---------------- kernel B: persistent HMMA gemm, atomic tile scheduler ----------------
#define SB_FULL 98304
#define SB_CONS 98328
#define SB_TILE 98352
#define SMEM_B  98368

__device__ __forceinline__ void issue_copies(uint32_t sb, int buf, int tile, int c) {
    const int nb = tile & 3, tb = tile >> 2;
    MBAR_EXPECT(sb + SB_FULL + buf * 8, 32768);
    bulk_g2s(sb + buf * 32768, g_h + ((size_t)(tb * NCHUNK + c) << 14), 16384, sb + SB_FULL + buf * 8);
    bulk_g2s(sb + buf * 32768 + 16384, g_w2s + ((size_t)(nb * NCHUNK + c) << 14), 16384, sb + SB_FULL + buf * 8);
}

__global__ void __launch_bounds__(256, 2)
ffq_gemm(const float* __restrict__ b2, float* __restrict__ out) {
    extern __shared__ char smem[];
    const uint32_t sb = smem_u32(smem);
    int* s_tile = (int*)(smem + SB_TILE);
    const int tid = threadIdx.x, wid = tid >> 5, lane = tid & 31;
    const int wm = wid & 1, wn = wid >> 1;

    if (tid == 0) {
#pragma unroll
        for (int s = 0; s < 3; ++s) {
            MBAR_INIT(sb + SB_FULL + s * 8, 1);
            MBAR_INIT(sb + SB_CONS + s * 8, 8);
        }
        s_tile[0] = atomicAdd(&g_ctr, 1);
    }
    __syncthreads();

    int t_cur = s_tile[0];
    if (t_cur >= NTILES) return;

    int t_next = 0;   // valid only on tid 0
    if (tid == 0) {
        t_next = atomicAdd(&g_ctr, 1);
#pragma unroll
        for (int s = 0; s < 3; ++s) issue_copies(sb, s, t_cur, s);
    }

    const uint32_t arow = (uint32_t)(wm * 64 + (lane & 15));
    const uint32_t abyte = (uint32_t)((lane >> 4) * 16);
    const uint32_t brow = (uint32_t)(wn * 32 + (lane & 7) + ((lane >> 4) & 1) * 8);
    const uint32_t bbyte = (uint32_t)(((lane >> 3) & 1) * 16);

    int cc = 0;   // global chunk counter (continuous ring position)
    for (;;) {
        float cf[16][4];
#pragma unroll
        for (int f = 0; f < 16; ++f)
#pragma unroll
            for (int i = 0; i < 4; ++i) cf[f][i] = 0.0f;

        for (int c = 0; c < NCHUNK; ++c, ++cc) {
            const int buf = cc % 3;
            const int ph = (cc / 3) & 1;
            MBAR_WAIT(sb + SB_FULL + buf * 8, ph);
            const uint32_t abase = sb + buf * 32768;
            const uint32_t bbase = abase + 16384;
#pragma unroll
            for (int k = 0; k < 4; ++k) {
                uint32_t af[4][4], bf[2][4];
#pragma unroll
                for (int mi = 0; mi < 4; ++mi)
                    LDMX4(af[mi], abase + SWZ((arow + mi * 16) * 128 + k * 32 + abyte));
#pragma unroll
                for (int bi = 0; bi < 2; ++bi)
                    LDMX4(bf[bi], bbase + SWZ((brow + bi * 16) * 128 + k * 32 + bbyte));
#pragma unroll
                for (int mi = 0; mi < 4; ++mi)
#pragma unroll
                    for (int ni = 0; ni < 4; ++ni)
                        MMA16816(cf[mi * 4 + ni], af[mi], bf[ni >> 1][(ni & 1) * 2], bf[ni >> 1][(ni & 1) * 2 + 1]);
            }
            __syncwarp();
            if (lane == 0) MBAR_ARRIVE(sb + SB_CONS + buf * 8);

            if (tid == 0) {
                // lookahead: stream chunk cc+3 -> (tile', c') ; issue if tile' valid
                int tgt_tile, tgt_c;
                if (c + 3 < NCHUNK) { tgt_tile = t_cur; tgt_c = c + 3; }
                else                { tgt_tile = t_next; tgt_c = c + 3 - NCHUNK; }
                if (tgt_tile < NTILES) {
                    MBAR_WAIT(sb + SB_CONS + buf * 8, ph);
                    issue_copies(sb, buf, tgt_tile, tgt_c);
                }
            }
        }

        // epilogue for t_cur
        {
            const int nb = t_cur & 3, tb = t_cur >> 2;
            const int rowbase = tb * 128 + wm * 64 + (lane >> 2);
            const int colbase = nb * 128 + wn * 32 + (lane & 3) * 2;
#pragma unroll
            for (int mi = 0; mi < 4; ++mi) {
#pragma unroll
                for (int ni = 0; ni < 4; ++ni) {
                    const int f = mi * 4 + ni;
                    const int col = colbase + ni * 8;
                    const float2 bv = *(const float2*)(b2 + col);
                    const int r0 = rowbase + mi * 16;
                    float2 o0, o1;
                    o0.x = cf[f][0] + bv.x; o0.y = cf[f][1] + bv.y;
                    o1.x = cf[f][2] + bv.x; o1.y = cf[f][3] + bv.y;
                    *(float2*)(out + (size_t)r0 * EDIM + col) = o0;
                    *(float2*)(out + (size_t)(r0 + 8) * EDIM + col) = o1;
                }
            }
        }

        // advance to next tile
        if (tid == 0) s_tile[0] = t_next;
        __syncthreads();
        t_cur = s_tile[0];
        if (t_cur >= NTILES) return;
        if (tid == 0) t_next = atomicAdd(&g_ctr, 1);
    }
}

extern "C" void kernel_launch(void* const* d_in, const int* in_sizes, int n_in,
                              void* d_out, int out_size) {
    const float* x     = (const float*)d_in[0];
    const float* theta = (const float*)d_in[1];
    const float* W1    = (const float*)d_in[2];
    const float* b1    = (const float*)d_in[3];
    const float* W2    = (const float*)d_in[4];
    const float* b2    = (const float*)d_in[5];
    float* out = (float*)d_out;

    cudaFuncSetAttribute(ffq_h, cudaFuncAttributeMaxDynamicSharedMemorySize, SMEM_A);
    cudaFuncSetAttribute(ffq_gemm, cudaFuncAttributeMaxDynamicSharedMemorySize, SMEM_B);

    ffq_h<<<NTOKB, 256, SMEM_A>>>(x, theta, W1, b1, W2);
    ffq_gemm<<<NWORKER, 256, SMEM_B>>>(b2, out);
}